// round 1
// baseline (speedup 1.0000x reference)
#include <cuda_runtime.h>
#include <cstdint>

// Problem constants (fixed by the dataset)
#define N_P   200000
#define N_A   100000
#define D_MP  64
#define E_NNZ 1200000
#define F_P   256
#define F_A   128

// ---------------------------------------------------------------------------
// Static scratch (allocation-free rule): 102.4 MB total
//   g_bufP : holds zp (projection of paper), later reused for g
//   g_bufA1: holds za (projection of author)
//   g_bufA2: holds h, later reused for h2
// ---------------------------------------------------------------------------
__device__ __align__(16) float g_bufP [(size_t)N_P * D_MP];
__device__ __align__(16) float g_bufA1[(size_t)N_A * D_MP];
__device__ __align__(16) float g_bufA2[(size_t)N_A * D_MP];

// ---------------------------------------------------------------------------
// Zero-fill (vectorized)
// ---------------------------------------------------------------------------
__global__ void zero_kernel(float4* __restrict__ p, int n4) {
    int i = blockIdx.x * blockDim.x + threadIdx.x;
    int stride = gridDim.x * blockDim.x;
    for (; i < n4; i += stride)
        p[i] = make_float4(0.f, 0.f, 0.f, 0.f);
}

// ---------------------------------------------------------------------------
// Dense projection: out[n, 64] = x[n, F] @ W[F, 64]   (chunked over K=128)
// Persistent blocks, W-chunk in smem (32 KB), warp computes 4 rows x 64 cols.
// n must be divisible by 4 (200000, 100000 both are).
// ---------------------------------------------------------------------------
template<int F, bool ACC>
__global__ void gemm64_kernel(const float* __restrict__ x,
                              const float* __restrict__ W,
                              float* __restrict__ out,
                              int n, int k0) {
    __shared__ float Wsh[128 * D_MP];   // 32 KB
    const int tid = threadIdx.x;
    for (int i = tid; i < 128 * D_MP; i += blockDim.x)
        Wsh[i] = W[(size_t)(k0 + (i >> 6)) * D_MP + (i & 63)];
    __syncthreads();

    const int lane  = tid & 31;
    const int warp  = tid >> 5;
    const int nwarp = (blockDim.x >> 5) * gridDim.x;
    const int gw    = blockIdx.x * (blockDim.x >> 5) + warp;
    const int c0    = lane * 2;
    const int ntile = n >> 2;   // 4 rows per tile

    for (int t = gw; t < ntile; t += nwarp) {
        const int r0 = t * 4;
        float acc[4][2] = {};
        const float* xb = x + (size_t)r0 * F + k0;

        for (int kk = 0; kk < 128; kk += 4) {
            float4 xv[4];
            #pragma unroll
            for (int j = 0; j < 4; j++)
                xv[j] = *(const float4*)(xb + (size_t)j * F + kk);
            #pragma unroll
            for (int u = 0; u < 4; u++) {
                float2 w2 = *(const float2*)&Wsh[(kk + u) * D_MP + c0];
                #pragma unroll
                for (int j = 0; j < 4; j++) {
                    float xs = (u == 0) ? xv[j].x : (u == 1) ? xv[j].y
                             : (u == 2) ? xv[j].z : xv[j].w;
                    acc[j][0] = fmaf(xs, w2.x, acc[j][0]);
                    acc[j][1] = fmaf(xs, w2.y, acc[j][1]);
                }
            }
        }
        #pragma unroll
        for (int j = 0; j < 4; j++) {
            float* o = out + (size_t)(r0 + j) * D_MP + c0;
            if (ACC) { o[0] += acc[j][0]; o[1] += acc[j][1]; }
            else     { o[0]  = acc[j][0]; o[1]  = acc[j][1]; }
        }
    }
}

// ---------------------------------------------------------------------------
// SpMM: out[row[e]] += val[e] * z[col[e]]  over d=64 columns.
// 16 threads per edge, one float4 each; scatter via red.global.add.v4.f32
// (16B vector reduction, no return -> 4x fewer atomic ops than scalar).
// ---------------------------------------------------------------------------
__global__ void spmm_kernel(const int*   __restrict__ row,
                            const int*   __restrict__ col,
                            const float* __restrict__ val,
                            const float* __restrict__ z,
                            float*       __restrict__ out,
                            int nnz) {
    int i = blockIdx.x * blockDim.x + threadIdx.x;
    int total = nnz * 16;
    if (i >= total) return;
    int e = i >> 4;
    int s = i & 15;
    int c = __ldg(col + e);
    int r = __ldg(row + e);
    float v = __ldg(val + e);
    float4 zv = __ldg((const float4*)(z + (size_t)c * D_MP) + s);
    float4 p;
    p.x = v * zv.x; p.y = v * zv.y; p.z = v * zv.z; p.w = v * zv.w;
    float* o = out + (size_t)r * D_MP + s * 4;
    asm volatile("red.global.add.v4.f32 [%0], {%1,%2,%3,%4};"
                 :: "l"(o), "f"(p.x), "f"(p.y), "f"(p.z), "f"(p.w)
                 : "memory");
}

// ---------------------------------------------------------------------------
// Launch
// ---------------------------------------------------------------------------
extern "C" void kernel_launch(void* const* d_in, const int* in_sizes, int n_in,
                              void* d_out, int out_size) {
    const float* x_paper  = (const float*)d_in[0];
    const float* x_author = (const float*)d_in[1];
    const float* W_paper  = (const float*)d_in[2];
    const float* W_author = (const float*)d_in[3];
    const int*   pa_row   = (const int*)  d_in[4];
    const int*   pa_col   = (const int*)  d_in[5];
    const float* pa_val   = (const float*)d_in[6];
    const int*   ap_row   = (const int*)  d_in[7];
    const int*   ap_col   = (const int*)  d_in[8];
    const float* ap_val   = (const float*)d_in[9];

    float* out       = (float*)d_out;
    float* out_pap   = out;
    float* out_papap = out + (size_t)N_P * D_MP;
    float* out_apa   = out + (size_t)2 * N_P * D_MP;

    float *bufP, *bufA1, *bufA2;
    cudaGetSymbolAddress((void**)&bufP,  g_bufP);
    cudaGetSymbolAddress((void**)&bufA1, g_bufA1);
    cudaGetSymbolAddress((void**)&bufA2, g_bufA2);

    const int ZB = 256;
    auto zgrid = [](size_t nfloat) {
        int n4 = (int)(nfloat / 4);
        int g = (n4 + ZB - 1) / ZB;
        return g > 16384 ? 16384 : g;
    };

    // zero d_out (pap, papap, apa) in one pass
    {
        size_t nf = (size_t)(2 * N_P + N_A) * D_MP;
        zero_kernel<<<zgrid(nf), ZB>>>((float4*)out, (int)(nf / 4));
    }
    // zero h buffer
    zero_kernel<<<zgrid((size_t)N_A * D_MP), ZB>>>((float4*)bufA2, N_A * D_MP / 4);

    // projections
    const int GB = 592;   // persistent blocks
    gemm64_kernel<F_P, false><<<GB, 256>>>(x_paper,  W_paper,  bufP,  N_P, 0);
    gemm64_kernel<F_P, true ><<<GB, 256>>>(x_paper,  W_paper,  bufP,  N_P, 128);
    gemm64_kernel<F_A, false><<<GB, 256>>>(x_author, W_author, bufA1, N_A, 0);

    const int SB = 256;
    const int sgrid = (E_NNZ * 16 + SB - 1) / SB;

    // P-A-P chain
    spmm_kernel<<<sgrid, SB>>>(pa_row, pa_col, pa_val, bufP,  bufA2,   E_NNZ); // h
    spmm_kernel<<<sgrid, SB>>>(ap_row, ap_col, ap_val, bufA2, out_pap, E_NNZ); // pap

    // P-A-P-A-P chain (reuse bufA2 for h2)
    zero_kernel<<<zgrid((size_t)N_A * D_MP), ZB>>>((float4*)bufA2, N_A * D_MP / 4);
    spmm_kernel<<<sgrid, SB>>>(pa_row, pa_col, pa_val, out_pap, bufA2,     E_NNZ); // h2
    spmm_kernel<<<sgrid, SB>>>(ap_row, ap_col, ap_val, bufA2,   out_papap, E_NNZ); // papap

    // A-P-A chain (reuse bufP for g; zp no longer needed)
    zero_kernel<<<zgrid((size_t)N_P * D_MP), ZB>>>((float4*)bufP, N_P * D_MP / 4);
    spmm_kernel<<<sgrid, SB>>>(ap_row, ap_col, ap_val, bufA1, bufP,    E_NNZ);  // g
    spmm_kernel<<<sgrid, SB>>>(pa_row, pa_col, pa_val, bufP,  out_apa, E_NNZ);  // apa
}

// round 2
// speedup vs baseline: 1.3497x; 1.3497x over previous
#include <cuda_runtime.h>
#include <cstdint>

#define N_P   200000
#define N_A   100000
#define D_MP  64
#define E_NNZ 1200000
#define F_P   256
#define F_A   128

// ---------------------------------------------------------------------------
// Static scratch
// ---------------------------------------------------------------------------
__device__ __align__(16) float g_bufP [(size_t)N_P * D_MP];   // zp, later g
__device__ __align__(16) float g_bufA1[(size_t)N_A * D_MP];   // za
__device__ __align__(16) float g_bufA2[(size_t)N_A * D_MP];   // h, later h2

// CSR scratch
__device__ int   g_pa_ptr[N_A + 1];
__device__ int   g_ap_ptr[N_P + 1];
__device__ int   g_pa_ccol[E_NNZ];
__device__ float g_pa_cval[E_NNZ];
__device__ int   g_ap_ccol[E_NNZ];
__device__ float g_ap_cval[E_NNZ];
// counters: [cntA (N_A)] [curA (N_A)] [cntP (N_P)] [curP (N_P)]
__device__ int   g_cnt[2 * (N_P + N_A)];
__device__ int   g_bsum[256];

// ---------------------------------------------------------------------------
// CSR build: histogram
// ---------------------------------------------------------------------------
__global__ void hist_kernel(const int* __restrict__ row, int* __restrict__ cnt, int nnz) {
    int i = blockIdx.x * blockDim.x + threadIdx.x;
    if (i < nnz) atomicAdd(&cnt[row[i]], 1);
}

// ---------------------------------------------------------------------------
// 3-pass exclusive scan over n counts -> rowptr[n+1]
// ---------------------------------------------------------------------------
#define SCAN_CHUNK 2048   // 256 threads x 8

__global__ void scan_pass1(const int* __restrict__ cnt, int* __restrict__ bs, int n) {
    __shared__ int sh[256];
    int base = blockIdx.x * SCAN_CHUNK;
    int t = threadIdx.x;
    int s = 0;
    #pragma unroll
    for (int j = 0; j < 8; j++) {
        int i = base + t * 8 + j;
        if (i < n) s += cnt[i];
    }
    sh[t] = s;
    __syncthreads();
    for (int off = 128; off > 0; off >>= 1) {
        if (t < off) sh[t] += sh[t + off];
        __syncthreads();
    }
    if (t == 0) bs[blockIdx.x] = sh[0];
}

__global__ void scan_pass2(int* __restrict__ bs, int nb) {   // nb <= 128
    __shared__ int sh[128];
    int t = threadIdx.x;
    int v = (t < nb) ? bs[t] : 0;
    sh[t] = v;
    __syncthreads();
    for (int off = 1; off < 128; off <<= 1) {
        int x = (t >= off) ? sh[t - off] : 0;
        __syncthreads();
        sh[t] += x;
        __syncthreads();
    }
    if (t < nb) bs[t] = sh[t] - v;   // exclusive
}

__global__ void scan_pass3(const int* __restrict__ cnt, const int* __restrict__ bs,
                           int* __restrict__ ptr, int n) {
    __shared__ int sh[256];
    int base = blockIdx.x * SCAN_CHUNK;
    int t = threadIdx.x;
    int v[8];
    int s = 0;
    #pragma unroll
    for (int j = 0; j < 8; j++) {
        int i = base + t * 8 + j;
        v[j] = (i < n) ? cnt[i] : 0;
        s += v[j];
    }
    sh[t] = s;
    __syncthreads();
    for (int off = 1; off < 256; off <<= 1) {
        int x = (t >= off) ? sh[t - off] : 0;
        __syncthreads();
        sh[t] += x;
        __syncthreads();
    }
    int ex = sh[t] - s + bs[blockIdx.x];
    #pragma unroll
    for (int j = 0; j < 8; j++) {
        int i = base + t * 8 + j;
        if (i < n) {
            ptr[i] = ex;
            ex += v[j];
            if (i == n - 1) ptr[n] = ex;
        }
    }
}

// ---------------------------------------------------------------------------
// CSR build: scatter edges into row segments
// ---------------------------------------------------------------------------
__global__ void scatter_kernel(const int* __restrict__ row, const int* __restrict__ col,
                               const float* __restrict__ val,
                               const int* __restrict__ ptr, int* __restrict__ cur,
                               int* __restrict__ ccol, float* __restrict__ cval, int nnz) {
    int i = blockIdx.x * blockDim.x + threadIdx.x;
    if (i >= nnz) return;
    int r = row[i];
    int p = ptr[r] + atomicAdd(&cur[r], 1);
    ccol[p] = col[i];
    cval[p] = val[i];
}

// ---------------------------------------------------------------------------
// Tiled SGEMM: out[n,64] = x[n,F] @ W[F,64]
// 128 threads, block tile 128x64, thread tile 8x8, BK=16, full K in registers.
// ---------------------------------------------------------------------------
template<int F>
__global__ __launch_bounds__(128) void gemm_tiled(const float* __restrict__ x,
                                                  const float* __restrict__ W,
                                                  float* __restrict__ out, int n) {
    __shared__ float xs[16][132];   // transposed x tile, pad 4 (16B-aligned rows)
    __shared__ float ws[16][64];

    const int t   = threadIdx.x;
    const int tx  = t & 7;          // col group: cols tx*8 .. +8
    const int ty  = t >> 3;         // row group: rows ty*8 .. +8
    const int row0 = blockIdx.x * 128;

    const int lr = t >> 2;          // x-load: row within 32-row slab
    const int lk = (t & 3) * 4;     // x-load: k offset
    const int wk = t >> 4;          // w-load: k row 0..7
    const int wc = (t & 15) * 4;    // w-load: col

    float acc[8][8] = {};

    for (int k0 = 0; k0 < F; k0 += 16) {
        #pragma unroll
        for (int i = 0; i < 4; i++) {
            int r = i * 32 + lr;
            int grow = row0 + r;
            float4 v = make_float4(0.f, 0.f, 0.f, 0.f);
            if (grow < n)
                v = *(const float4*)(x + (size_t)grow * F + k0 + lk);
            xs[lk + 0][r] = v.x;
            xs[lk + 1][r] = v.y;
            xs[lk + 2][r] = v.z;
            xs[lk + 3][r] = v.w;
        }
        *(float4*)&ws[wk][wc]     = *(const float4*)(W + (size_t)(k0 + wk) * D_MP + wc);
        *(float4*)&ws[wk + 8][wc] = *(const float4*)(W + (size_t)(k0 + wk + 8) * D_MP + wc);
        __syncthreads();

        #pragma unroll
        for (int k = 0; k < 16; k++) {
            float xf[8], wf[8];
            *(float4*)&xf[0] = *(const float4*)&xs[k][ty * 8];
            *(float4*)&xf[4] = *(const float4*)&xs[k][ty * 8 + 4];
            *(float4*)&wf[0] = *(const float4*)&ws[k][tx * 8];
            *(float4*)&wf[4] = *(const float4*)&ws[k][tx * 8 + 4];
            #pragma unroll
            for (int i = 0; i < 8; i++)
                #pragma unroll
                for (int j = 0; j < 8; j++)
                    acc[i][j] = fmaf(xf[i], wf[j], acc[i][j]);
        }
        __syncthreads();
    }

    #pragma unroll
    for (int i = 0; i < 8; i++) {
        int grow = row0 + ty * 8 + i;
        if (grow < n) {
            float4 v0 = make_float4(acc[i][0], acc[i][1], acc[i][2], acc[i][3]);
            float4 v1 = make_float4(acc[i][4], acc[i][5], acc[i][6], acc[i][7]);
            *(float4*)(out + (size_t)grow * D_MP + tx * 8)     = v0;
            *(float4*)(out + (size_t)grow * D_MP + tx * 8 + 4) = v1;
        }
    }
}

// ---------------------------------------------------------------------------
// CSR SpMM: one warp per output row, 2 edges per iteration (16 lanes each),
// register accumulation, single coalesced write. No atomics, no zero-fill.
// ---------------------------------------------------------------------------
__global__ void spmm_csr_kernel(const int* __restrict__ ptr,
                                const int* __restrict__ ccol,
                                const float* __restrict__ cval,
                                const float* __restrict__ z,
                                float* __restrict__ out, int nrows) {
    int w = (blockIdx.x * blockDim.x + threadIdx.x) >> 5;
    if (w >= nrows) return;
    int lane = threadIdx.x & 31;
    int half = lane >> 4;
    int s    = lane & 15;

    int beg = ptr[w], end = ptr[w + 1];
    float4 acc = make_float4(0.f, 0.f, 0.f, 0.f);
    for (int e = beg + half; e < end; e += 2) {
        int   c = __ldg(ccol + e);
        float v = __ldg(cval + e);
        float4 zv = __ldg((const float4*)(z + (size_t)c * D_MP) + s);
        acc.x = fmaf(v, zv.x, acc.x);
        acc.y = fmaf(v, zv.y, acc.y);
        acc.z = fmaf(v, zv.z, acc.z);
        acc.w = fmaf(v, zv.w, acc.w);
    }
    acc.x += __shfl_xor_sync(0xffffffffu, acc.x, 16);
    acc.y += __shfl_xor_sync(0xffffffffu, acc.y, 16);
    acc.z += __shfl_xor_sync(0xffffffffu, acc.z, 16);
    acc.w += __shfl_xor_sync(0xffffffffu, acc.w, 16);
    if (half == 0)
        *((float4*)(out + (size_t)w * D_MP) + s) = acc;
}

// ---------------------------------------------------------------------------
// Launch
// ---------------------------------------------------------------------------
extern "C" void kernel_launch(void* const* d_in, const int* in_sizes, int n_in,
                              void* d_out, int out_size) {
    const float* x_paper  = (const float*)d_in[0];
    const float* x_author = (const float*)d_in[1];
    const float* W_paper  = (const float*)d_in[2];
    const float* W_author = (const float*)d_in[3];
    const int*   pa_row   = (const int*)  d_in[4];
    const int*   pa_col   = (const int*)  d_in[5];
    const float* pa_val   = (const float*)d_in[6];
    const int*   ap_row   = (const int*)  d_in[7];
    const int*   ap_col   = (const int*)  d_in[8];
    const float* ap_val   = (const float*)d_in[9];

    float* out       = (float*)d_out;
    float* out_pap   = out;
    float* out_papap = out + (size_t)N_P * D_MP;
    float* out_apa   = out + (size_t)2 * N_P * D_MP;

    float *bufP, *bufA1, *bufA2;
    int *pa_ptr, *ap_ptr, *pa_ccol, *ap_ccol, *cnt, *bsum;
    float *pa_cval, *ap_cval;
    cudaGetSymbolAddress((void**)&bufP,    g_bufP);
    cudaGetSymbolAddress((void**)&bufA1,   g_bufA1);
    cudaGetSymbolAddress((void**)&bufA2,   g_bufA2);
    cudaGetSymbolAddress((void**)&pa_ptr,  g_pa_ptr);
    cudaGetSymbolAddress((void**)&ap_ptr,  g_ap_ptr);
    cudaGetSymbolAddress((void**)&pa_ccol, g_pa_ccol);
    cudaGetSymbolAddress((void**)&pa_cval, g_pa_cval);
    cudaGetSymbolAddress((void**)&ap_ccol, g_ap_ccol);
    cudaGetSymbolAddress((void**)&ap_cval, g_ap_cval);
    cudaGetSymbolAddress((void**)&cnt,     g_cnt);
    cudaGetSymbolAddress((void**)&bsum,    g_bsum);

    int* cntA = cnt;
    int* curA = cnt + N_A;
    int* cntP = cnt + 2 * N_A;
    int* curP = cnt + 2 * N_A + N_P;

    // ---- CSR build ----
    cudaMemsetAsync(cnt, 0, (size_t)2 * (N_P + N_A) * sizeof(int));

    const int HB = 256;
    const int hgrid = (E_NNZ + HB - 1) / HB;
    hist_kernel<<<hgrid, HB>>>(pa_row, cntA, E_NNZ);
    hist_kernel<<<hgrid, HB>>>(ap_row, cntP, E_NNZ);

    const int nbA = (N_A + SCAN_CHUNK - 1) / SCAN_CHUNK;  // 49
    const int nbP = (N_P + SCAN_CHUNK - 1) / SCAN_CHUNK;  // 98
    scan_pass1<<<nbA, 256>>>(cntA, bsum, N_A);
    scan_pass2<<<1, 128>>>(bsum, nbA);
    scan_pass3<<<nbA, 256>>>(cntA, bsum, pa_ptr, N_A);
    scan_pass1<<<nbP, 256>>>(cntP, bsum, N_P);
    scan_pass2<<<1, 128>>>(bsum, nbP);
    scan_pass3<<<nbP, 256>>>(cntP, bsum, ap_ptr, N_P);

    scatter_kernel<<<hgrid, HB>>>(pa_row, pa_col, pa_val, pa_ptr, curA,
                                  pa_ccol, pa_cval, E_NNZ);
    scatter_kernel<<<hgrid, HB>>>(ap_row, ap_col, ap_val, ap_ptr, curP,
                                  ap_ccol, ap_cval, E_NNZ);

    // ---- Projections ----
    gemm_tiled<F_P><<<(N_P + 127) / 128, 128>>>(x_paper,  W_paper,  bufP,  N_P);
    gemm_tiled<F_A><<<(N_A + 127) / 128, 128>>>(x_author, W_author, bufA1, N_A);

    // ---- SpMM chains (warp per row) ----
    auto sblocks = [](int nrows) { return (nrows * 32 + 255) / 256; };

    // P-A-P
    spmm_csr_kernel<<<sblocks(N_A), 256>>>(pa_ptr, pa_ccol, pa_cval, bufP,  bufA2,   N_A);
    spmm_csr_kernel<<<sblocks(N_P), 256>>>(ap_ptr, ap_ccol, ap_cval, bufA2, out_pap, N_P);
    // P-A-P-A-P
    spmm_csr_kernel<<<sblocks(N_A), 256>>>(pa_ptr, pa_ccol, pa_cval, out_pap, bufA2,     N_A);
    spmm_csr_kernel<<<sblocks(N_P), 256>>>(ap_ptr, ap_ccol, ap_cval, bufA2,   out_papap, N_P);
    // A-P-A
    spmm_csr_kernel<<<sblocks(N_P), 256>>>(ap_ptr, ap_ccol, ap_cval, bufA1, bufP,    N_P);
    spmm_csr_kernel<<<sblocks(N_A), 256>>>(pa_ptr, pa_ccol, pa_cval, bufP,  out_apa, N_A);
}

// round 5
// speedup vs baseline: 1.4356x; 1.0636x over previous
#include <cuda_runtime.h>
#include <cstdint>

#define N_P   200000
#define N_A   100000
#define D_MP  64
#define E_NNZ 1200000
#define F_P   256
#define F_A   128

// ===========================================================================
// Static scratch
// ===========================================================================
__device__ __align__(16) float g_bufP [(size_t)N_P * D_MP];   // zp, later g
__device__ __align__(16) float g_bufA1[(size_t)N_A * D_MP];   // za
__device__ __align__(16) float g_bufA2[(size_t)N_A * D_MP];   // h, later h2

// CSR scratch
__device__ int   g_pa_ptr[N_A + 1];
__device__ int   g_ap_ptr[N_P + 1];
__device__ int   g_pa_ccol[E_NNZ];
__device__ float g_pa_cval[E_NNZ];
__device__ int   g_ap_ccol[E_NNZ];
__device__ float g_ap_cval[E_NNZ];
__device__ int   g_cnt[2 * (N_P + N_A)];
__device__ int   g_bsumA[128];
__device__ int   g_bsumP[128];

// ===========================================================================
// tf32 helpers
// ===========================================================================
__device__ __forceinline__ uint32_t f2tf32(float f) {
    uint32_t r;
    asm("cvt.rna.tf32.f32 %0, %1;" : "=r"(r) : "f"(f));
    return r;
}

__device__ __forceinline__ void mma_tf32(float* d, const uint32_t* a, const uint32_t* b) {
    asm volatile("mma.sync.aligned.m16n8k8.row.col.f32.tf32.tf32.f32 "
                 "{%0,%1,%2,%3}, {%4,%5,%6,%7}, {%8,%9}, {%0,%1,%2,%3};"
                 : "+f"(d[0]), "+f"(d[1]), "+f"(d[2]), "+f"(d[3])
                 : "r"(a[0]), "r"(a[1]), "r"(a[2]), "r"(a[3]),
                   "r"(b[0]), "r"(b[1]));
}

// ===========================================================================
// Tensor-core GEMM via mma.sync (3xTF32 split, ~fp32 accuracy)
// out[n,64] = x[n,F] @ W[F,64]
// Block: 128 threads (4 warps); block tile 128 rows x 64 cols.
// Warp computes 32 rows x 64 cols: 2 m-tiles (16) x 8 n-tiles (8), k-step 8.
// W resident in smem (stride 72 floats); x staged per 32-k chunk (stride 36).
// ===========================================================================
template<int F>
__global__ __launch_bounds__(128) void gemm_mma(const float* __restrict__ x,
                                                const float* __restrict__ W,
                                                float* __restrict__ out, int n) {
    extern __shared__ float sm[];
    float* ws = sm;              // [F][72]
    float* xs = sm + F * 72;     // [128][36]

    const int t    = threadIdx.x;
    const int lane = t & 31;
    const int wid  = t >> 5;
    const int tig  = lane & 3;   // thread-in-group (k idx)
    const int gid  = lane >> 2;  // group id (row / n idx)
    const int row0 = blockIdx.x * 128;

    // Load W into smem: ws[k][n], row stride 72
    for (int i = t; i < F * 16; i += 128) {
        int k  = i >> 4;
        int c4 = (i & 15) << 2;
        float4 v = *(const float4*)(W + (size_t)k * 64 + c4);
        *(float4*)(ws + k * 72 + c4) = v;
    }

    float acc[2][8][4];
    #pragma unroll
    for (int mt = 0; mt < 2; mt++)
        #pragma unroll
        for (int nt = 0; nt < 8; nt++)
            #pragma unroll
            for (int q = 0; q < 4; q++) acc[mt][nt][q] = 0.f;

    for (int kc = 0; kc < F; kc += 32) {
        __syncthreads();   // first iter: W ready; later: xs consumers done
        // stage xs: 128 rows x 32 k floats, coalesced (8 threads per row)
        #pragma unroll
        for (int i = 0; i < 8; i++) {
            int r    = i * 16 + (t >> 3);
            int c4   = (t & 7) << 2;
            int grow = row0 + r;
            float4 v = make_float4(0.f, 0.f, 0.f, 0.f);
            if (grow < n)
                v = *(const float4*)(x + (size_t)grow * F + kc + c4);
            *(float4*)(xs + r * 36 + c4) = v;
        }
        __syncthreads();

        #pragma unroll
        for (int ks = 0; ks < 4; ks++) {
            const int k0 = ks * 8;        // chunk-local k for A
            const int kg = kc + k0;       // GLOBAL k for B (bug fix)

            // B fragments (all 8 n-tiles), split hi/lo
            uint32_t bh[8][2], bl[8][2];
            #pragma unroll
            for (int nt = 0; nt < 8; nt++) {
                float b0 = ws[(kg + tig)     * 72 + nt * 8 + gid];
                float b1 = ws[(kg + tig + 4) * 72 + nt * 8 + gid];
                bh[nt][0] = __float_as_uint(b0) & 0xFFFFE000u;
                bl[nt][0] = f2tf32(b0 - __uint_as_float(bh[nt][0]));
                bh[nt][1] = __float_as_uint(b1) & 0xFFFFE000u;
                bl[nt][1] = f2tf32(b1 - __uint_as_float(bh[nt][1]));
            }

            #pragma unroll
            for (int mt = 0; mt < 2; mt++) {
                int r = wid * 32 + mt * 16 + gid;
                float a0 = xs[r       * 36 + k0 + tig];
                float a1 = xs[(r + 8) * 36 + k0 + tig];
                float a2 = xs[r       * 36 + k0 + tig + 4];
                float a3 = xs[(r + 8) * 36 + k0 + tig + 4];
                uint32_t ah[4], al[4];
                ah[0] = __float_as_uint(a0) & 0xFFFFE000u;
                ah[1] = __float_as_uint(a1) & 0xFFFFE000u;
                ah[2] = __float_as_uint(a2) & 0xFFFFE000u;
                ah[3] = __float_as_uint(a3) & 0xFFFFE000u;
                al[0] = f2tf32(a0 - __uint_as_float(ah[0]));
                al[1] = f2tf32(a1 - __uint_as_float(ah[1]));
                al[2] = f2tf32(a2 - __uint_as_float(ah[2]));
                al[3] = f2tf32(a3 - __uint_as_float(ah[3]));

                #pragma unroll
                for (int nt = 0; nt < 8; nt++) {
                    mma_tf32(acc[mt][nt], ah, bh[nt]);
                    mma_tf32(acc[mt][nt], al, bh[nt]);
                    mma_tf32(acc[mt][nt], ah, bl[nt]);
                }
            }
        }
    }

    // Epilogue: D frag (16x8): c0,c1 -> row gid, cols 2*tig; c2,c3 -> row gid+8
    #pragma unroll
    for (int mt = 0; mt < 2; mt++) {
        int rbase = row0 + wid * 32 + mt * 16 + gid;
        #pragma unroll
        for (int half = 0; half < 2; half++) {
            int grow = rbase + half * 8;
            if (grow < n) {
                float* o = out + (size_t)grow * D_MP + tig * 2;
                #pragma unroll
                for (int nt = 0; nt < 8; nt++) {
                    float2 v = half ? make_float2(acc[mt][nt][2], acc[mt][nt][3])
                                    : make_float2(acc[mt][nt][0], acc[mt][nt][1]);
                    *(float2*)(o + nt * 8) = v;
                }
            }
        }
    }
}

// ===========================================================================
// CSR build
// ===========================================================================
__global__ void hist_kernel(const int* __restrict__ row, int* __restrict__ cnt, int nnz) {
    int i = blockIdx.x * blockDim.x + threadIdx.x;
    if (i < nnz) atomicAdd(&cnt[row[i]], 1);
}

#define SCAN_CHUNK 2048

__global__ void scan_pass1(const int* __restrict__ cnt, int* __restrict__ bs, int n) {
    __shared__ int sh[256];
    int base = blockIdx.x * SCAN_CHUNK;
    int t = threadIdx.x;
    int s = 0;
    #pragma unroll
    for (int j = 0; j < 8; j++) {
        int i = base + t * 8 + j;
        if (i < n) s += cnt[i];
    }
    sh[t] = s;
    __syncthreads();
    for (int off = 128; off > 0; off >>= 1) {
        if (t < off) sh[t] += sh[t + off];
        __syncthreads();
    }
    if (t == 0) bs[blockIdx.x] = sh[0];
}

__global__ void scan_pass2_dual(int* __restrict__ bsA, int nbA,
                                int* __restrict__ bsP, int nbP) {
    __shared__ int sh[128];
    int* bs = blockIdx.x ? bsP : bsA;
    int nb  = blockIdx.x ? nbP : nbA;
    int t = threadIdx.x;
    int v = (t < nb) ? bs[t] : 0;
    sh[t] = v;
    __syncthreads();
    for (int off = 1; off < 128; off <<= 1) {
        int xx = (t >= off) ? sh[t - off] : 0;
        __syncthreads();
        sh[t] += xx;
        __syncthreads();
    }
    if (t < nb) bs[t] = sh[t] - v;
}

__global__ void scan_pass3(const int* __restrict__ cnt, const int* __restrict__ bs,
                           int* __restrict__ ptr, int n) {
    __shared__ int sh[256];
    int base = blockIdx.x * SCAN_CHUNK;
    int t = threadIdx.x;
    int v[8];
    int s = 0;
    #pragma unroll
    for (int j = 0; j < 8; j++) {
        int i = base + t * 8 + j;
        v[j] = (i < n) ? cnt[i] : 0;
        s += v[j];
    }
    sh[t] = s;
    __syncthreads();
    for (int off = 1; off < 256; off <<= 1) {
        int xx = (t >= off) ? sh[t - off] : 0;
        __syncthreads();
        sh[t] += xx;
        __syncthreads();
    }
    int ex = sh[t] - s + bs[blockIdx.x];
    #pragma unroll
    for (int j = 0; j < 8; j++) {
        int i = base + t * 8 + j;
        if (i < n) {
            ptr[i] = ex;
            ex += v[j];
            if (i == n - 1) ptr[n] = ex;
        }
    }
}

__global__ void scatter_kernel(const int* __restrict__ row, const int* __restrict__ col,
                               const float* __restrict__ val,
                               const int* __restrict__ ptr, int* __restrict__ cur,
                               int* __restrict__ ccol, float* __restrict__ cval, int nnz) {
    int i = blockIdx.x * blockDim.x + threadIdx.x;
    if (i >= nnz) return;
    int r = row[i];
    int p = ptr[r] + atomicAdd(&cur[r], 1);
    ccol[p] = col[i];
    cval[p] = val[i];
}

// ===========================================================================
// CSR SpMM: one warp per output row, register accumulation, no atomics.
// ===========================================================================
__global__ void spmm_csr_kernel(const int* __restrict__ ptr,
                                const int* __restrict__ ccol,
                                const float* __restrict__ cval,
                                const float* __restrict__ z,
                                float* __restrict__ out, int nrows) {
    int w = (blockIdx.x * blockDim.x + threadIdx.x) >> 5;
    if (w >= nrows) return;
    int lane = threadIdx.x & 31;
    int half = lane >> 4;
    int s    = lane & 15;

    int beg = ptr[w], end = ptr[w + 1];
    float4 acc = make_float4(0.f, 0.f, 0.f, 0.f);
    for (int e = beg + half; e < end; e += 2) {
        int   c = __ldg(ccol + e);
        float v = __ldg(cval + e);
        float4 zv = __ldg((const float4*)(z + (size_t)c * D_MP) + s);
        acc.x = fmaf(v, zv.x, acc.x);
        acc.y = fmaf(v, zv.y, acc.y);
        acc.z = fmaf(v, zv.z, acc.z);
        acc.w = fmaf(v, zv.w, acc.w);
    }
    acc.x += __shfl_xor_sync(0xffffffffu, acc.x, 16);
    acc.y += __shfl_xor_sync(0xffffffffu, acc.y, 16);
    acc.z += __shfl_xor_sync(0xffffffffu, acc.z, 16);
    acc.w += __shfl_xor_sync(0xffffffffu, acc.w, 16);
    if (half == 0)
        *((float4*)(out + (size_t)w * D_MP) + s) = acc;
}

// ===========================================================================
// Launch
// ===========================================================================
extern "C" void kernel_launch(void* const* d_in, const int* in_sizes, int n_in,
                              void* d_out, int out_size) {
    const float* x_paper  = (const float*)d_in[0];
    const float* x_author = (const float*)d_in[1];
    const float* W_paper  = (const float*)d_in[2];
    const float* W_author = (const float*)d_in[3];
    const int*   pa_row   = (const int*)  d_in[4];
    const int*   pa_col   = (const int*)  d_in[5];
    const float* pa_val   = (const float*)d_in[6];
    const int*   ap_row   = (const int*)  d_in[7];
    const int*   ap_col   = (const int*)  d_in[8];
    const float* ap_val   = (const float*)d_in[9];

    float* out       = (float*)d_out;
    float* out_pap   = out;
    float* out_papap = out + (size_t)N_P * D_MP;
    float* out_apa   = out + (size_t)2 * N_P * D_MP;

    float *bufP, *bufA1, *bufA2;
    int *pa_ptr, *ap_ptr, *pa_ccol, *ap_ccol, *cnt, *bsumA, *bsumP;
    float *pa_cval, *ap_cval;
    cudaGetSymbolAddress((void**)&bufP,    g_bufP);
    cudaGetSymbolAddress((void**)&bufA1,   g_bufA1);
    cudaGetSymbolAddress((void**)&bufA2,   g_bufA2);
    cudaGetSymbolAddress((void**)&pa_ptr,  g_pa_ptr);
    cudaGetSymbolAddress((void**)&ap_ptr,  g_ap_ptr);
    cudaGetSymbolAddress((void**)&pa_ccol, g_pa_ccol);
    cudaGetSymbolAddress((void**)&pa_cval, g_pa_cval);
    cudaGetSymbolAddress((void**)&ap_ccol, g_ap_ccol);
    cudaGetSymbolAddress((void**)&ap_cval, g_ap_cval);
    cudaGetSymbolAddress((void**)&cnt,     g_cnt);
    cudaGetSymbolAddress((void**)&bsumA,   g_bsumA);
    cudaGetSymbolAddress((void**)&bsumP,   g_bsumP);

    int* cntA = cnt;
    int* curA = cnt + N_A;
    int* cntP = cnt + 2 * N_A;
    int* curP = cnt + 2 * N_A + N_P;

    // dynamic smem for the mma GEMMs
    const int smemP = (F_P * 72 + 128 * 36) * 4;   // 92160
    const int smemA = (F_A * 72 + 128 * 36) * 4;   // 55296
    cudaFuncSetAttribute(gemm_mma<F_P>, cudaFuncAttributeMaxDynamicSharedMemorySize, smemP);
    cudaFuncSetAttribute(gemm_mma<F_A>, cudaFuncAttributeMaxDynamicSharedMemorySize, smemA);

    // ---- CSR build ----
    cudaMemsetAsync(cnt, 0, (size_t)2 * (N_P + N_A) * sizeof(int));

    const int HB = 256;
    const int hgrid = (E_NNZ + HB - 1) / HB;
    hist_kernel<<<hgrid, HB>>>(pa_row, cntA, E_NNZ);
    hist_kernel<<<hgrid, HB>>>(ap_row, cntP, E_NNZ);

    const int nbA = (N_A + SCAN_CHUNK - 1) / SCAN_CHUNK;
    const int nbP = (N_P + SCAN_CHUNK - 1) / SCAN_CHUNK;
    scan_pass1<<<nbA, 256>>>(cntA, bsumA, N_A);
    scan_pass1<<<nbP, 256>>>(cntP, bsumP, N_P);
    scan_pass2_dual<<<2, 128>>>(bsumA, nbA, bsumP, nbP);
    scan_pass3<<<nbA, 256>>>(cntA, bsumA, pa_ptr, N_A);
    scan_pass3<<<nbP, 256>>>(cntP, bsumP, ap_ptr, N_P);

    scatter_kernel<<<hgrid, HB>>>(pa_row, pa_col, pa_val, pa_ptr, curA,
                                  pa_ccol, pa_cval, E_NNZ);
    scatter_kernel<<<hgrid, HB>>>(ap_row, ap_col, ap_val, ap_ptr, curP,
                                  ap_ccol, ap_cval, E_NNZ);

    // ---- Projections via mma.sync (3xTF32) ----
    gemm_mma<F_P><<<(N_P + 127) / 128, 128, smemP>>>(x_paper,  W_paper,  bufP,  N_P);
    gemm_mma<F_A><<<(N_A + 127) / 128, 128, smemA>>>(x_author, W_author, bufA1, N_A);

    // ---- SpMM chains (warp per row) ----
    auto sblocks = [](int nrows) { return (nrows * 32 + 255) / 256; };

    // P-A-P
    spmm_csr_kernel<<<sblocks(N_A), 256>>>(pa_ptr, pa_ccol, pa_cval, bufP,  bufA2,   N_A);
    spmm_csr_kernel<<<sblocks(N_P), 256>>>(ap_ptr, ap_ccol, ap_cval, bufA2, out_pap, N_P);
    // P-A-P-A-P
    spmm_csr_kernel<<<sblocks(N_A), 256>>>(pa_ptr, pa_ccol, pa_cval, out_pap, bufA2,     N_A);
    spmm_csr_kernel<<<sblocks(N_P), 256>>>(ap_ptr, ap_ccol, ap_cval, bufA2,   out_papap, N_P);
    // A-P-A
    spmm_csr_kernel<<<sblocks(N_P), 256>>>(ap_ptr, ap_ccol, ap_cval, bufA1, bufP,    N_P);
    spmm_csr_kernel<<<sblocks(N_A), 256>>>(pa_ptr, pa_ccol, pa_cval, bufP,  out_apa, N_A);
}

// round 6
// speedup vs baseline: 1.5514x; 1.0806x over previous
#include <cuda_runtime.h>
#include <cuda_bf16.h>
#include <cstdint>

#define N_P   200000
#define N_A   100000
#define D_MP  64
#define E_NNZ 1200000
#define F_P   256
#define F_A   128

// ===========================================================================
// Static scratch
// ===========================================================================
__device__ __align__(16) float g_bufP [(size_t)N_P * D_MP];   // zp, later g
__device__ __align__(16) float g_bufA1[(size_t)N_A * D_MP];   // za
__device__ __align__(16) float g_bufA2[(size_t)N_A * D_MP];   // h, later h2

// CSR scratch
__device__ int   g_pa_ptr[N_A + 1];
__device__ int   g_ap_ptr[N_P + 1];
__device__ int   g_pa_ccol[E_NNZ];
__device__ float g_pa_cval[E_NNZ];
__device__ int   g_ap_ccol[E_NNZ];
__device__ float g_ap_cval[E_NNZ];
__device__ int   g_cnt[2 * (N_P + N_A)];
__device__ int   g_bsumA[128];
__device__ int   g_bsumP[128];

// ===========================================================================
// bf16 split helpers
// ===========================================================================
// Returns uint2: .x = packed bf16x2 (hi(a) lo-half, hi(b) hi-half),
//                .y = packed bf16x2 of the residuals.
__device__ __forceinline__ uint2 split_pack(float a, float b) {
    float fa = __bfloat162float(__float2bfloat16_rn(a));
    float fb = __bfloat162float(__float2bfloat16_rn(b));
    uint32_t hi, lo;
    asm("cvt.rn.bf16x2.f32 %0, %1, %2;" : "=r"(hi) : "f"(fb), "f"(fa));
    asm("cvt.rn.bf16x2.f32 %0, %1, %2;" : "=r"(lo) : "f"(b - fb), "f"(a - fa));
    return make_uint2(hi, lo);
}

__device__ __forceinline__ void mma_bf16(float* d, const uint32_t* a, const uint32_t* b) {
    asm volatile("mma.sync.aligned.m16n8k16.row.col.f32.bf16.bf16.f32 "
                 "{%0,%1,%2,%3}, {%4,%5,%6,%7}, {%8,%9}, {%0,%1,%2,%3};"
                 : "+f"(d[0]), "+f"(d[1]), "+f"(d[2]), "+f"(d[3])
                 : "r"(a[0]), "r"(a[1]), "r"(a[2]), "r"(a[3]),
                   "r"(b[0]), "r"(b[1]));
}

// ===========================================================================
// Tensor-core GEMM via mma.sync m16n8k16 (3x bf16 split, ~1e-5 accuracy)
// out[n,64] = x[n,F] @ W[F,64]
// 256 threads (8 warps); block tile 128 rows x 64 cols; warp tile 16x64.
// Operands pre-split hi/lo and packed bf16x2 during staging; one LDS.64
// yields both hi and lo fragments. Row stride 20*uint2 -> conflict-free.
// ===========================================================================
template<int F>
__global__ __launch_bounds__(256) void gemm_bf16x3(const float* __restrict__ x,
                                                   const float* __restrict__ W,
                                                   float* __restrict__ out, int n) {
    __shared__ uint2 ws[64 * 20];     // W chunk: [n=64][kpair<=16]
    __shared__ uint2 xs[128 * 20];    // x chunk: [r=128][kpair=16]

    const int t    = threadIdx.x;
    const int lane = t & 31;
    const int wid  = t >> 5;
    const int tig  = lane & 3;
    const int gid  = lane >> 2;
    const int row0 = blockIdx.x * 128;

    float acc[8][4];
    #pragma unroll
    for (int nt = 0; nt < 8; nt++)
        #pragma unroll
        for (int q = 0; q < 4; q++) acc[nt][q] = 0.f;

    for (int kc = 0; kc < F; kc += 32) {
        __syncthreads();
        // stage W chunk: 16 kpairs x 64 n  (coalesced over n)
        #pragma unroll
        for (int j = 0; j < 4; j++) {
            int idx = j * 256 + t;
            int nn  = idx & 63;
            int kp  = idx >> 6;           // 0..15
            int k   = kc + kp * 2;
            float w0 = W[(size_t)k * 64 + nn];
            float w1 = W[(size_t)(k + 1) * 64 + nn];
            ws[nn * 20 + kp] = split_pack(w0, w1);
        }
        // stage x chunk: 128 rows x 16 kpairs (16 threads per row, float2)
        #pragma unroll
        for (int j = 0; j < 8; j++) {
            int idx = j * 256 + t;
            int r   = idx >> 4;
            int kp  = idx & 15;
            int grow = row0 + r;
            float2 v = make_float2(0.f, 0.f);
            if (grow < n)
                v = *(const float2*)(x + (size_t)grow * F + kc + kp * 2);
            xs[r * 20 + kp] = split_pack(v.x, v.y);
        }
        __syncthreads();

        #pragma unroll
        for (int ks = 0; ks < 2; ks++) {
            const int p0 = ks * 8 + tig;
            const int p1 = p0 + 4;
            const int r0 = wid * 16 + gid;
            uint2 qa0 = xs[r0 * 20 + p0];
            uint2 qa1 = xs[(r0 + 8) * 20 + p0];
            uint2 qa2 = xs[r0 * 20 + p1];
            uint2 qa3 = xs[(r0 + 8) * 20 + p1];
            uint32_t ah[4] = {qa0.x, qa1.x, qa2.x, qa3.x};
            uint32_t al[4] = {qa0.y, qa1.y, qa2.y, qa3.y};

            #pragma unroll
            for (int nt = 0; nt < 8; nt++) {
                int nn = nt * 8 + gid;
                uint2 qb0 = ws[nn * 20 + p0];
                uint2 qb1 = ws[nn * 20 + p1];
                uint32_t bh[2] = {qb0.x, qb1.x};
                uint32_t bl[2] = {qb0.y, qb1.y};
                mma_bf16(acc[nt], ah, bh);
                mma_bf16(acc[nt], al, bh);
                mma_bf16(acc[nt], ah, bl);
            }
        }
    }

    // Epilogue: D frag 16x8: c0,c1 -> row gid, cols 2tig; c2,c3 -> row gid+8
    #pragma unroll
    for (int half = 0; half < 2; half++) {
        int grow = row0 + wid * 16 + gid + half * 8;
        if (grow < n) {
            float* o = out + (size_t)grow * D_MP + tig * 2;
            #pragma unroll
            for (int nt = 0; nt < 8; nt++) {
                float2 v = half ? make_float2(acc[nt][2], acc[nt][3])
                                : make_float2(acc[nt][0], acc[nt][1]);
                *(float2*)(o + nt * 8) = v;
            }
        }
    }
}

// ===========================================================================
// CSR build (dual kernels cover both matrices in one launch)
// ===========================================================================
__global__ void hist_dual(const int* __restrict__ rowA, const int* __restrict__ rowP,
                          int* __restrict__ cntA, int* __restrict__ cntP) {
    int i = blockIdx.x * blockDim.x + threadIdx.x;
    if (i < E_NNZ) {
        atomicAdd(&cntA[rowA[i]], 1);
    } else if (i < 2 * E_NNZ) {
        atomicAdd(&cntP[rowP[i - E_NNZ]], 1);
    }
}

#define SCAN_CHUNK 2048

// blocks [0, nbA) scan cntA -> bsA; blocks [nbA, nbA+nbP) scan cntP -> bsP
__global__ void scan_pass1_dual(const int* __restrict__ cntA, int* __restrict__ bsA, int nA,
                                const int* __restrict__ cntP, int* __restrict__ bsP, int nP,
                                int nbA) {
    __shared__ int sh[256];
    const int* cnt = (blockIdx.x < nbA) ? cntA : cntP;
    int*       bs  = (blockIdx.x < nbA) ? bsA  : bsP;
    int        n   = (blockIdx.x < nbA) ? nA   : nP;
    int        blk = (blockIdx.x < nbA) ? blockIdx.x : blockIdx.x - nbA;
    int base = blk * SCAN_CHUNK;
    int t = threadIdx.x;
    int s = 0;
    #pragma unroll
    for (int j = 0; j < 8; j++) {
        int i = base + t * 8 + j;
        if (i < n) s += cnt[i];
    }
    sh[t] = s;
    __syncthreads();
    for (int off = 128; off > 0; off >>= 1) {
        if (t < off) sh[t] += sh[t + off];
        __syncthreads();
    }
    if (t == 0) bs[blk] = sh[0];
}

__global__ void scan_pass2_dual(int* __restrict__ bsA, int nbA,
                                int* __restrict__ bsP, int nbP) {
    __shared__ int sh[128];
    int* bs = blockIdx.x ? bsP : bsA;
    int nb  = blockIdx.x ? nbP : nbA;
    int t = threadIdx.x;
    int v = (t < nb) ? bs[t] : 0;
    sh[t] = v;
    __syncthreads();
    for (int off = 1; off < 128; off <<= 1) {
        int xx = (t >= off) ? sh[t - off] : 0;
        __syncthreads();
        sh[t] += xx;
        __syncthreads();
    }
    if (t < nb) bs[t] = sh[t] - v;
}

__global__ void scan_pass3_dual(const int* __restrict__ cntA, const int* __restrict__ bsA,
                                int* __restrict__ ptrA, int nA,
                                const int* __restrict__ cntP, const int* __restrict__ bsP,
                                int* __restrict__ ptrP, int nP, int nbA) {
    __shared__ int sh[256];
    const int* cnt = (blockIdx.x < nbA) ? cntA : cntP;
    const int* bs  = (blockIdx.x < nbA) ? bsA  : bsP;
    int*       ptr = (blockIdx.x < nbA) ? ptrA : ptrP;
    int        n   = (blockIdx.x < nbA) ? nA   : nP;
    int        blk = (blockIdx.x < nbA) ? blockIdx.x : blockIdx.x - nbA;
    int base = blk * SCAN_CHUNK;
    int t = threadIdx.x;
    int v[8];
    int s = 0;
    #pragma unroll
    for (int j = 0; j < 8; j++) {
        int i = base + t * 8 + j;
        v[j] = (i < n) ? cnt[i] : 0;
        s += v[j];
    }
    sh[t] = s;
    __syncthreads();
    for (int off = 1; off < 256; off <<= 1) {
        int xx = (t >= off) ? sh[t - off] : 0;
        __syncthreads();
        sh[t] += xx;
        __syncthreads();
    }
    int ex = sh[t] - s + bs[blk];
    #pragma unroll
    for (int j = 0; j < 8; j++) {
        int i = base + t * 8 + j;
        if (i < n) {
            ptr[i] = ex;
            ex += v[j];
            if (i == n - 1) ptr[n] = ex;
        }
    }
}

__global__ void scatter_dual(const int* __restrict__ rowA, const int* __restrict__ colA,
                             const float* __restrict__ valA,
                             const int* __restrict__ ptrA, int* __restrict__ curA,
                             int* __restrict__ ccolA, float* __restrict__ cvalA,
                             const int* __restrict__ rowP, const int* __restrict__ colP,
                             const float* __restrict__ valP,
                             const int* __restrict__ ptrP, int* __restrict__ curP,
                             int* __restrict__ ccolP, float* __restrict__ cvalP) {
    int i = blockIdx.x * blockDim.x + threadIdx.x;
    if (i < E_NNZ) {
        int r = rowA[i];
        int p = ptrA[r] + atomicAdd(&curA[r], 1);
        ccolA[p] = colA[i];
        cvalA[p] = valA[i];
    } else if (i < 2 * E_NNZ) {
        int j = i - E_NNZ;
        int r = rowP[j];
        int p = ptrP[r] + atomicAdd(&curP[r], 1);
        ccolP[p] = colP[j];
        cvalP[p] = valP[j];
    }
}

// ===========================================================================
// CSR SpMM: one warp per output row, register accumulation, no atomics.
// ===========================================================================
__global__ void spmm_csr_kernel(const int* __restrict__ ptr,
                                const int* __restrict__ ccol,
                                const float* __restrict__ cval,
                                const float* __restrict__ z,
                                float* __restrict__ out, int nrows) {
    int w = (blockIdx.x * blockDim.x + threadIdx.x) >> 5;
    if (w >= nrows) return;
    int lane = threadIdx.x & 31;
    int half = lane >> 4;
    int s    = lane & 15;

    int beg = ptr[w], end = ptr[w + 1];
    float4 acc = make_float4(0.f, 0.f, 0.f, 0.f);
    for (int e = beg + half; e < end; e += 2) {
        int   c = __ldg(ccol + e);
        float v = __ldg(cval + e);
        float4 zv = __ldg((const float4*)(z + (size_t)c * D_MP) + s);
        acc.x = fmaf(v, zv.x, acc.x);
        acc.y = fmaf(v, zv.y, acc.y);
        acc.z = fmaf(v, zv.z, acc.z);
        acc.w = fmaf(v, zv.w, acc.w);
    }
    acc.x += __shfl_xor_sync(0xffffffffu, acc.x, 16);
    acc.y += __shfl_xor_sync(0xffffffffu, acc.y, 16);
    acc.z += __shfl_xor_sync(0xffffffffu, acc.z, 16);
    acc.w += __shfl_xor_sync(0xffffffffu, acc.w, 16);
    if (half == 0)
        *((float4*)(out + (size_t)w * D_MP) + s) = acc;
}

// ===========================================================================
// Launch
// ===========================================================================
extern "C" void kernel_launch(void* const* d_in, const int* in_sizes, int n_in,
                              void* d_out, int out_size) {
    const float* x_paper  = (const float*)d_in[0];
    const float* x_author = (const float*)d_in[1];
    const float* W_paper  = (const float*)d_in[2];
    const float* W_author = (const float*)d_in[3];
    const int*   pa_row   = (const int*)  d_in[4];
    const int*   pa_col   = (const int*)  d_in[5];
    const float* pa_val   = (const float*)d_in[6];
    const int*   ap_row   = (const int*)  d_in[7];
    const int*   ap_col   = (const int*)  d_in[8];
    const float* ap_val   = (const float*)d_in[9];

    float* out       = (float*)d_out;
    float* out_pap   = out;
    float* out_papap = out + (size_t)N_P * D_MP;
    float* out_apa   = out + (size_t)2 * N_P * D_MP;

    float *bufP, *bufA1, *bufA2;
    int *pa_ptr, *ap_ptr, *pa_ccol, *ap_ccol, *cnt, *bsumA, *bsumP;
    float *pa_cval, *ap_cval;
    cudaGetSymbolAddress((void**)&bufP,    g_bufP);
    cudaGetSymbolAddress((void**)&bufA1,   g_bufA1);
    cudaGetSymbolAddress((void**)&bufA2,   g_bufA2);
    cudaGetSymbolAddress((void**)&pa_ptr,  g_pa_ptr);
    cudaGetSymbolAddress((void**)&ap_ptr,  g_ap_ptr);
    cudaGetSymbolAddress((void**)&pa_ccol, g_pa_ccol);
    cudaGetSymbolAddress((void**)&pa_cval, g_pa_cval);
    cudaGetSymbolAddress((void**)&ap_ccol, g_ap_ccol);
    cudaGetSymbolAddress((void**)&ap_cval, g_ap_cval);
    cudaGetSymbolAddress((void**)&cnt,     g_cnt);
    cudaGetSymbolAddress((void**)&bsumA,   g_bsumA);
    cudaGetSymbolAddress((void**)&bsumP,   g_bsumP);

    int* cntA = cnt;
    int* curA = cnt + N_A;
    int* cntP = cnt + 2 * N_A;
    int* curP = cnt + 2 * N_A + N_P;

    // ---- CSR build ----
    cudaMemsetAsync(cnt, 0, (size_t)2 * (N_P + N_A) * sizeof(int));

    const int HB = 256;
    const int dgrid = (2 * E_NNZ + HB - 1) / HB;
    hist_dual<<<dgrid, HB>>>(pa_row, ap_row, cntA, cntP);

    const int nbA = (N_A + SCAN_CHUNK - 1) / SCAN_CHUNK;
    const int nbP = (N_P + SCAN_CHUNK - 1) / SCAN_CHUNK;
    scan_pass1_dual<<<nbA + nbP, 256>>>(cntA, bsumA, N_A, cntP, bsumP, N_P, nbA);
    scan_pass2_dual<<<2, 128>>>(bsumA, nbA, bsumP, nbP);
    scan_pass3_dual<<<nbA + nbP, 256>>>(cntA, bsumA, pa_ptr, N_A,
                                        cntP, bsumP, ap_ptr, N_P, nbA);

    scatter_dual<<<dgrid, HB>>>(pa_row, pa_col, pa_val, pa_ptr, curA, pa_ccol, pa_cval,
                                ap_row, ap_col, ap_val, ap_ptr, curP, ap_ccol, ap_cval);

    // ---- Projections via mma.sync m16n8k16 (3x bf16 split) ----
    gemm_bf16x3<F_P><<<(N_P + 127) / 128, 256>>>(x_paper,  W_paper,  bufP,  N_P);
    gemm_bf16x3<F_A><<<(N_A + 127) / 128, 256>>>(x_author, W_author, bufA1, N_A);

    // ---- SpMM chains (warp per row) ----
    auto sblocks = [](int nrows) { return (nrows * 32 + 255) / 256; };

    // P-A-P
    spmm_csr_kernel<<<sblocks(N_A), 256>>>(pa_ptr, pa_ccol, pa_cval, bufP,  bufA2,   N_A);
    spmm_csr_kernel<<<sblocks(N_P), 256>>>(ap_ptr, ap_ccol, ap_cval, bufA2, out_pap, N_P);
    // P-A-P-A-P
    spmm_csr_kernel<<<sblocks(N_A), 256>>>(pa_ptr, pa_ccol, pa_cval, out_pap, bufA2,     N_A);
    spmm_csr_kernel<<<sblocks(N_P), 256>>>(ap_ptr, ap_ccol, ap_cval, bufA2,   out_papap, N_P);
    // A-P-A
    spmm_csr_kernel<<<sblocks(N_P), 256>>>(ap_ptr, ap_ccol, ap_cval, bufA1, bufP,    N_P);
    spmm_csr_kernel<<<sblocks(N_A), 256>>>(pa_ptr, pa_ccol, pa_cval, bufP,  out_apa, N_A);
}

// round 7
// speedup vs baseline: 1.6525x; 1.0652x over previous
#include <cuda_runtime.h>
#include <cuda_bf16.h>
#include <cstdint>

#define N_P   200000
#define N_A   100000
#define D_MP  64
#define E_NNZ 1200000
#define F_P   256
#define F_A   128

// ===========================================================================
// Static scratch
// ===========================================================================
__device__ __align__(16) float g_bufP [(size_t)N_P * D_MP];   // zp, later g
__device__ __align__(16) float g_bufA1[(size_t)N_A * D_MP];   // za
__device__ __align__(16) float g_bufA2[(size_t)N_A * D_MP];   // h, later h2

// CSR scratch
__device__ int   g_pa_ptr[N_A + 1];
__device__ int   g_ap_ptr[N_P + 1];
__device__ int   g_pa_ccol[E_NNZ];
__device__ float g_pa_cval[E_NNZ];
__device__ int   g_ap_ccol[E_NNZ];
__device__ float g_ap_cval[E_NNZ];
__device__ int   g_cnt[2 * (N_P + N_A)];
__device__ int   g_bsumA[128];
__device__ int   g_bsumP[128];

// ===========================================================================
// bf16 split helpers
// ===========================================================================
__device__ __forceinline__ uint2 split_pack(float a, float b) {
    float fa = __bfloat162float(__float2bfloat16_rn(a));
    float fb = __bfloat162float(__float2bfloat16_rn(b));
    uint32_t hi, lo;
    asm("cvt.rn.bf16x2.f32 %0, %1, %2;" : "=r"(hi) : "f"(fb), "f"(fa));
    asm("cvt.rn.bf16x2.f32 %0, %1, %2;" : "=r"(lo) : "f"(b - fb), "f"(a - fa));
    return make_uint2(hi, lo);
}

__device__ __forceinline__ void mma_bf16(float* d, const uint32_t* a, const uint32_t* b) {
    asm volatile("mma.sync.aligned.m16n8k16.row.col.f32.bf16.bf16.f32 "
                 "{%0,%1,%2,%3}, {%4,%5,%6,%7}, {%8,%9}, {%0,%1,%2,%3};"
                 : "+f"(d[0]), "+f"(d[1]), "+f"(d[2]), "+f"(d[3])
                 : "r"(a[0]), "r"(a[1]), "r"(a[2]), "r"(a[3]),
                   "r"(b[0]), "r"(b[1]));
}

// ===========================================================================
// Tensor-core GEMM via mma.sync m16n8k16 (3x bf16 split, ~1e-5 accuracy)
// out[n,64] = x[n,F] @ W[F,64]
// 256 threads (8 warps); block tile 256 rows x 64 cols; warp tile 32x64
// (2 m-tiles x 8 n-tiles) -> B fragments amortized over 2 m-tiles:
// 48 LDS.64 per 96 MMAs (1.0 smem-cyc/MMA, balanced with HMMA issue).
// ===========================================================================
template<int F>
__global__ __launch_bounds__(256) void gemm_bf16x3(const float* __restrict__ x,
                                                   const float* __restrict__ W,
                                                   float* __restrict__ out, int n) {
    __shared__ uint2 ws[64 * 20];      // W chunk: [n=64][kpair 16]
    __shared__ uint2 xs[256 * 20];     // x chunk: [r=256][kpair 16]

    const int t    = threadIdx.x;
    const int lane = t & 31;
    const int wid  = t >> 5;
    const int tig  = lane & 3;
    const int gid  = lane >> 2;
    const int row0 = blockIdx.x * 256;

    float acc[2][8][4];
    #pragma unroll
    for (int mt = 0; mt < 2; mt++)
        #pragma unroll
        for (int nt = 0; nt < 8; nt++)
            #pragma unroll
            for (int q = 0; q < 4; q++) acc[mt][nt][q] = 0.f;

    for (int kc = 0; kc < F; kc += 32) {
        __syncthreads();
        // stage W chunk: 16 kpairs x 64 n (coalesced LDG over n)
        #pragma unroll
        for (int j = 0; j < 4; j++) {
            int idx = j * 256 + t;
            int nn  = idx & 63;
            int kp  = idx >> 6;
            int k   = kc + kp * 2;
            float w0 = W[(size_t)k * 64 + nn];
            float w1 = W[(size_t)(k + 1) * 64 + nn];
            ws[nn * 20 + kp] = split_pack(w0, w1);
        }
        // stage x chunk: 256 rows x 16 kpairs (16 threads per row, float2)
        #pragma unroll
        for (int j = 0; j < 16; j++) {
            int idx = j * 256 + t;
            int r   = idx >> 4;
            int kp  = idx & 15;
            int grow = row0 + r;
            float2 v = make_float2(0.f, 0.f);
            if (grow < n)
                v = *(const float2*)(x + (size_t)grow * F + kc + kp * 2);
            xs[r * 20 + kp] = split_pack(v.x, v.y);
        }
        __syncthreads();

        #pragma unroll
        for (int ks = 0; ks < 2; ks++) {
            const int p0 = ks * 8 + tig;
            const int p1 = p0 + 4;

            // A fragments for both m-tiles
            uint32_t ah[2][4], al[2][4];
            #pragma unroll
            for (int mt = 0; mt < 2; mt++) {
                int r0 = wid * 32 + mt * 16 + gid;
                uint2 qa0 = xs[r0 * 20 + p0];
                uint2 qa1 = xs[(r0 + 8) * 20 + p0];
                uint2 qa2 = xs[r0 * 20 + p1];
                uint2 qa3 = xs[(r0 + 8) * 20 + p1];
                ah[mt][0] = qa0.x; ah[mt][1] = qa1.x; ah[mt][2] = qa2.x; ah[mt][3] = qa3.x;
                al[mt][0] = qa0.y; al[mt][1] = qa1.y; al[mt][2] = qa2.y; al[mt][3] = qa3.y;
            }

            #pragma unroll
            for (int nt = 0; nt < 8; nt++) {
                int nn = nt * 8 + gid;
                uint2 qb0 = ws[nn * 20 + p0];
                uint2 qb1 = ws[nn * 20 + p1];
                uint32_t bh[2] = {qb0.x, qb1.x};
                uint32_t bl[2] = {qb0.y, qb1.y};
                #pragma unroll
                for (int mt = 0; mt < 2; mt++) {
                    mma_bf16(acc[mt][nt], ah[mt], bh);
                    mma_bf16(acc[mt][nt], al[mt], bh);
                    mma_bf16(acc[mt][nt], ah[mt], bl);
                }
            }
        }
    }

    // Epilogue
    #pragma unroll
    for (int mt = 0; mt < 2; mt++) {
        #pragma unroll
        for (int half = 0; half < 2; half++) {
            int grow = row0 + wid * 32 + mt * 16 + gid + half * 8;
            if (grow < n) {
                float* o = out + (size_t)grow * D_MP + tig * 2;
                #pragma unroll
                for (int nt = 0; nt < 8; nt++) {
                    float2 v = half ? make_float2(acc[mt][nt][2], acc[mt][nt][3])
                                    : make_float2(acc[mt][nt][0], acc[mt][nt][1]);
                    *(float2*)(o + nt * 8) = v;
                }
            }
        }
    }
}

// ===========================================================================
// CSR build
// ===========================================================================
__global__ void hist_dual(const int* __restrict__ rowA, const int* __restrict__ rowP,
                          int* __restrict__ cntA, int* __restrict__ cntP) {
    int i = blockIdx.x * blockDim.x + threadIdx.x;
    if (i < E_NNZ) {
        atomicAdd(&cntA[rowA[i]], 1);
    } else if (i < 2 * E_NNZ) {
        atomicAdd(&cntP[rowP[i - E_NNZ]], 1);
    }
}

#define SCAN_CHUNK 2048

__global__ void scan_pass1_dual(const int* __restrict__ cntA, int* __restrict__ bsA, int nA,
                                const int* __restrict__ cntP, int* __restrict__ bsP, int nP,
                                int nbA) {
    __shared__ int sh[256];
    const int* cnt = (blockIdx.x < nbA) ? cntA : cntP;
    int*       bs  = (blockIdx.x < nbA) ? bsA  : bsP;
    int        n   = (blockIdx.x < nbA) ? nA   : nP;
    int        blk = (blockIdx.x < nbA) ? blockIdx.x : blockIdx.x - nbA;
    int base = blk * SCAN_CHUNK;
    int t = threadIdx.x;
    int s = 0;
    #pragma unroll
    for (int j = 0; j < 8; j++) {
        int i = base + t * 8 + j;
        if (i < n) s += cnt[i];
    }
    sh[t] = s;
    __syncthreads();
    for (int off = 128; off > 0; off >>= 1) {
        if (t < off) sh[t] += sh[t + off];
        __syncthreads();
    }
    if (t == 0) bs[blk] = sh[0];
}

__global__ void scan_pass2_dual(int* __restrict__ bsA, int nbA,
                                int* __restrict__ bsP, int nbP) {
    __shared__ int sh[128];
    int* bs = blockIdx.x ? bsP : bsA;
    int nb  = blockIdx.x ? nbP : nbA;
    int t = threadIdx.x;
    int v = (t < nb) ? bs[t] : 0;
    sh[t] = v;
    __syncthreads();
    for (int off = 1; off < 128; off <<= 1) {
        int xx = (t >= off) ? sh[t - off] : 0;
        __syncthreads();
        sh[t] += xx;
        __syncthreads();
    }
    if (t < nb) bs[t] = sh[t] - v;
}

__global__ void scan_pass3_dual(const int* __restrict__ cntA, const int* __restrict__ bsA,
                                int* __restrict__ ptrA, int nA,
                                const int* __restrict__ cntP, const int* __restrict__ bsP,
                                int* __restrict__ ptrP, int nP, int nbA) {
    __shared__ int sh[256];
    const int* cnt = (blockIdx.x < nbA) ? cntA : cntP;
    const int* bs  = (blockIdx.x < nbA) ? bsA  : bsP;
    int*       ptr = (blockIdx.x < nbA) ? ptrA : ptrP;
    int        n   = (blockIdx.x < nbA) ? nA   : nP;
    int        blk = (blockIdx.x < nbA) ? blockIdx.x : blockIdx.x - nbA;
    int base = blk * SCAN_CHUNK;
    int t = threadIdx.x;
    int v[8];
    int s = 0;
    #pragma unroll
    for (int j = 0; j < 8; j++) {
        int i = base + t * 8 + j;
        v[j] = (i < n) ? cnt[i] : 0;
        s += v[j];
    }
    sh[t] = s;
    __syncthreads();
    for (int off = 1; off < 256; off <<= 1) {
        int xx = (t >= off) ? sh[t - off] : 0;
        __syncthreads();
        sh[t] += xx;
        __syncthreads();
    }
    int ex = sh[t] - s + bs[blk];
    #pragma unroll
    for (int j = 0; j < 8; j++) {
        int i = base + t * 8 + j;
        if (i < n) {
            ptr[i] = ex;
            ex += v[j];
            if (i == n - 1) ptr[n] = ex;
        }
    }
}

__global__ void scatter_dual(const int* __restrict__ rowA, const int* __restrict__ colA,
                             const float* __restrict__ valA,
                             const int* __restrict__ ptrA, int* __restrict__ curA,
                             int* __restrict__ ccolA, float* __restrict__ cvalA,
                             const int* __restrict__ rowP, const int* __restrict__ colP,
                             const float* __restrict__ valP,
                             const int* __restrict__ ptrP, int* __restrict__ curP,
                             int* __restrict__ ccolP, float* __restrict__ cvalP) {
    int i = blockIdx.x * blockDim.x + threadIdx.x;
    if (i < E_NNZ) {
        int r = rowA[i];
        int p = ptrA[r] + atomicAdd(&curA[r], 1);
        ccolA[p] = colA[i];
        cvalA[p] = valA[i];
    } else if (i < 2 * E_NNZ) {
        int j = i - E_NNZ;
        int r = rowP[j];
        int p = ptrP[r] + atomicAdd(&curP[r], 1);
        ccolP[p] = colP[j];
        cvalP[p] = valP[j];
    }
}

// ===========================================================================
// CSR SpMM: warp per row, 2-way unrolled edge loop per 16-lane half
// (4 independent gathers in flight per warp), no atomics.
// ===========================================================================
__global__ void spmm_csr_kernel(const int* __restrict__ ptr,
                                const int* __restrict__ ccol,
                                const float* __restrict__ cval,
                                const float* __restrict__ z,
                                float* __restrict__ out, int nrows) {
    int w = (blockIdx.x * blockDim.x + threadIdx.x) >> 5;
    if (w >= nrows) return;
    int lane = threadIdx.x & 31;
    int half = lane >> 4;
    int s    = lane & 15;

    int beg = ptr[w], end = ptr[w + 1];
    float4 acc0 = make_float4(0.f, 0.f, 0.f, 0.f);
    float4 acc1 = make_float4(0.f, 0.f, 0.f, 0.f);

    int e = beg + half;
    for (; e + 2 < end; e += 4) {
        int   c0 = __ldg(ccol + e);
        float v0 = __ldg(cval + e);
        int   c1 = __ldg(ccol + e + 2);
        float v1 = __ldg(cval + e + 2);
        float4 z0 = __ldg((const float4*)(z + (size_t)c0 * D_MP) + s);
        float4 z1 = __ldg((const float4*)(z + (size_t)c1 * D_MP) + s);
        acc0.x = fmaf(v0, z0.x, acc0.x);
        acc0.y = fmaf(v0, z0.y, acc0.y);
        acc0.z = fmaf(v0, z0.z, acc0.z);
        acc0.w = fmaf(v0, z0.w, acc0.w);
        acc1.x = fmaf(v1, z1.x, acc1.x);
        acc1.y = fmaf(v1, z1.y, acc1.y);
        acc1.z = fmaf(v1, z1.z, acc1.z);
        acc1.w = fmaf(v1, z1.w, acc1.w);
    }
    if (e < end) {
        int   c = __ldg(ccol + e);
        float v = __ldg(cval + e);
        float4 zv = __ldg((const float4*)(z + (size_t)c * D_MP) + s);
        acc0.x = fmaf(v, zv.x, acc0.x);
        acc0.y = fmaf(v, zv.y, acc0.y);
        acc0.z = fmaf(v, zv.z, acc0.z);
        acc0.w = fmaf(v, zv.w, acc0.w);
    }
    acc0.x += acc1.x; acc0.y += acc1.y; acc0.z += acc1.z; acc0.w += acc1.w;

    acc0.x += __shfl_xor_sync(0xffffffffu, acc0.x, 16);
    acc0.y += __shfl_xor_sync(0xffffffffu, acc0.y, 16);
    acc0.z += __shfl_xor_sync(0xffffffffu, acc0.z, 16);
    acc0.w += __shfl_xor_sync(0xffffffffu, acc0.w, 16);
    if (half == 0)
        *((float4*)(out + (size_t)w * D_MP) + s) = acc0;
}

// ===========================================================================
// Launch
// ===========================================================================
extern "C" void kernel_launch(void* const* d_in, const int* in_sizes, int n_in,
                              void* d_out, int out_size) {
    const float* x_paper  = (const float*)d_in[0];
    const float* x_author = (const float*)d_in[1];
    const float* W_paper  = (const float*)d_in[2];
    const float* W_author = (const float*)d_in[3];
    const int*   pa_row   = (const int*)  d_in[4];
    const int*   pa_col   = (const int*)  d_in[5];
    const float* pa_val   = (const float*)d_in[6];
    const int*   ap_row   = (const int*)  d_in[7];
    const int*   ap_col   = (const int*)  d_in[8];
    const float* ap_val   = (const float*)d_in[9];

    float* out       = (float*)d_out;
    float* out_pap   = out;
    float* out_papap = out + (size_t)N_P * D_MP;
    float* out_apa   = out + (size_t)2 * N_P * D_MP;

    float *bufP, *bufA1, *bufA2;
    int *pa_ptr, *ap_ptr, *pa_ccol, *ap_ccol, *cnt, *bsumA, *bsumP;
    float *pa_cval, *ap_cval;
    cudaGetSymbolAddress((void**)&bufP,    g_bufP);
    cudaGetSymbolAddress((void**)&bufA1,   g_bufA1);
    cudaGetSymbolAddress((void**)&bufA2,   g_bufA2);
    cudaGetSymbolAddress((void**)&pa_ptr,  g_pa_ptr);
    cudaGetSymbolAddress((void**)&ap_ptr,  g_ap_ptr);
    cudaGetSymbolAddress((void**)&pa_ccol, g_pa_ccol);
    cudaGetSymbolAddress((void**)&pa_cval, g_pa_cval);
    cudaGetSymbolAddress((void**)&ap_ccol, g_ap_ccol);
    cudaGetSymbolAddress((void**)&ap_cval, g_ap_cval);
    cudaGetSymbolAddress((void**)&cnt,     g_cnt);
    cudaGetSymbolAddress((void**)&bsumA,   g_bsumA);
    cudaGetSymbolAddress((void**)&bsumP,   g_bsumP);

    int* cntA = cnt;
    int* curA = cnt + N_A;
    int* cntP = cnt + 2 * N_A;
    int* curP = cnt + 2 * N_A + N_P;

    cudaMemsetAsync(cnt, 0, (size_t)2 * (N_P + N_A) * sizeof(int));

    const int HB = 256;
    const int dgrid = (2 * E_NNZ + HB - 1) / HB;
    const int nbA = (N_A + SCAN_CHUNK - 1) / SCAN_CHUNK;
    const int nbP = (N_P + SCAN_CHUNK - 1) / SCAN_CHUNK;

    // kernel order chosen so the 4th kernel node (ncu capture slot) is gemmP
    hist_dual<<<dgrid, HB>>>(pa_row, ap_row, cntA, cntP);                       // 0
    scan_pass1_dual<<<nbA + nbP, 256>>>(cntA, bsumA, N_A, cntP, bsumP, N_P, nbA); // 1
    scan_pass2_dual<<<2, 128>>>(bsumA, nbA, bsumP, nbP);                        // 2
    gemm_bf16x3<F_P><<<(N_P + 255) / 256, 256>>>(x_paper,  W_paper,  bufP,  N_P); // 3 <- profiled
    gemm_bf16x3<F_A><<<(N_A + 255) / 256, 256>>>(x_author, W_author, bufA1, N_A); // 4
    scan_pass3_dual<<<nbA + nbP, 256>>>(cntA, bsumA, pa_ptr, N_A,
                                        cntP, bsumP, ap_ptr, N_P, nbA);         // 5
    scatter_dual<<<dgrid, HB>>>(pa_row, pa_col, pa_val, pa_ptr, curA, pa_ccol, pa_cval,
                                ap_row, ap_col, ap_val, ap_ptr, curP, ap_ccol, ap_cval); // 6

    auto sblocks = [](int nrows) { return (nrows * 32 + 255) / 256; };

    // P-A-P
    spmm_csr_kernel<<<sblocks(N_A), 256>>>(pa_ptr, pa_ccol, pa_cval, bufP,  bufA2,   N_A);
    spmm_csr_kernel<<<sblocks(N_P), 256>>>(ap_ptr, ap_ccol, ap_cval, bufA2, out_pap, N_P);
    // P-A-P-A-P
    spmm_csr_kernel<<<sblocks(N_A), 256>>>(pa_ptr, pa_ccol, pa_cval, out_pap, bufA2,     N_A);
    spmm_csr_kernel<<<sblocks(N_P), 256>>>(ap_ptr, ap_ccol, ap_cval, bufA2,   out_papap, N_P);
    // A-P-A
    spmm_csr_kernel<<<sblocks(N_P), 256>>>(ap_ptr, ap_ccol, ap_cval, bufA1, bufP,    N_P);
    spmm_csr_kernel<<<sblocks(N_A), 256>>>(pa_ptr, pa_ccol, pa_cval, bufP,  out_apa, N_A);
}

// round 8
// speedup vs baseline: 1.7668x; 1.0692x over previous
#include <cuda_runtime.h>
#include <cuda_bf16.h>
#include <cstdint>

#define N_P   200000
#define N_A   100000
#define D_MP  64
#define E_NNZ 1200000
#define F_P   256
#define F_A   128

// ===========================================================================
// Static scratch
// ===========================================================================
__device__ __align__(16) float g_bufP [(size_t)N_P * D_MP];   // zp, later g
__device__ __align__(16) float g_bufA1[(size_t)N_A * D_MP];   // za
__device__ __align__(16) float g_bufA2[(size_t)N_A * D_MP];   // h, later h2

// CSR scratch
__device__ int   g_pa_ptr[N_A + 1];
__device__ int   g_ap_ptr[N_P + 1];
__device__ int   g_pa_ccol[E_NNZ];
__device__ float g_pa_cval[E_NNZ];
__device__ int   g_ap_ccol[E_NNZ];
__device__ float g_ap_cval[E_NNZ];
__device__ int   g_cnt[2 * (N_P + N_A)];
__device__ int   g_bsumA[128];
__device__ int   g_bsumP[128];

// ===========================================================================
// bf16 split helpers
// ===========================================================================
__device__ __forceinline__ uint2 split_pack(float a, float b) {
    float fa = __bfloat162float(__float2bfloat16_rn(a));
    float fb = __bfloat162float(__float2bfloat16_rn(b));
    uint32_t hi, lo;
    asm("cvt.rn.bf16x2.f32 %0, %1, %2;" : "=r"(hi) : "f"(fb), "f"(fa));
    asm("cvt.rn.bf16x2.f32 %0, %1, %2;" : "=r"(lo) : "f"(b - fb), "f"(a - fa));
    return make_uint2(hi, lo);
}

__device__ __forceinline__ void mma_bf16(float* d, const uint32_t* a, const uint32_t* b) {
    asm volatile("mma.sync.aligned.m16n8k16.row.col.f32.bf16.bf16.f32 "
                 "{%0,%1,%2,%3}, {%4,%5,%6,%7}, {%8,%9}, {%0,%1,%2,%3};"
                 : "+f"(d[0]), "+f"(d[1]), "+f"(d[2]), "+f"(d[3])
                 : "r"(a[0]), "r"(a[1]), "r"(a[2]), "r"(a[3]),
                   "r"(b[0]), "r"(b[1]));
}

// ===========================================================================
// Tensor-core GEMM via mma.sync m16n8k16 (3x bf16 split, ~1e-5 accuracy)
// out[n,64] = x[n,F] @ W[F,64]
// 256 threads (8 warps); block tile 128 rows x 64 cols; warp tile 32x32
// (warp grid 4m x 2n; 2 m-tiles x 4 n-tiles per warp).
// acc = 32 regs -> fits 2 CTAs/SM (launch_bounds cap 128 regs), occ 25%.
// Per k16 per warp: 8 A-LDS.64 + 8 B-LDS.64 per 24 MMAs.
// ===========================================================================
template<int F>
__global__ __launch_bounds__(256, 2) void gemm_bf16x3(const float* __restrict__ x,
                                                      const float* __restrict__ W,
                                                      float* __restrict__ out, int n) {
    __shared__ uint2 ws[64 * 20];      // W chunk: [n=64][kpair 16]
    __shared__ uint2 xs[128 * 20];     // x chunk: [r=128][kpair 16]

    const int t    = threadIdx.x;
    const int lane = t & 31;
    const int wid  = t >> 5;
    const int wm   = wid >> 1;        // 0..3: row group
    const int wn   = wid & 1;         // 0..1: col group
    const int tig  = lane & 3;
    const int gid  = lane >> 2;
    const int row0 = blockIdx.x * 128;

    float acc[2][4][4];
    #pragma unroll
    for (int mt = 0; mt < 2; mt++)
        #pragma unroll
        for (int nt = 0; nt < 4; nt++)
            #pragma unroll
            for (int q = 0; q < 4; q++) acc[mt][nt][q] = 0.f;

    for (int kc = 0; kc < F; kc += 32) {
        __syncthreads();
        // stage W chunk: 16 kpairs x 64 n (coalesced LDG over n)
        #pragma unroll
        for (int j = 0; j < 4; j++) {
            int idx = j * 256 + t;
            int nn  = idx & 63;
            int kp  = idx >> 6;
            int k   = kc + kp * 2;
            float w0 = W[(size_t)k * 64 + nn];
            float w1 = W[(size_t)(k + 1) * 64 + nn];
            ws[nn * 20 + kp] = split_pack(w0, w1);
        }
        // stage x chunk: 128 rows x 16 kpairs (16 threads per row, float2)
        #pragma unroll
        for (int j = 0; j < 8; j++) {
            int idx = j * 256 + t;
            int r   = idx >> 4;
            int kp  = idx & 15;
            int grow = row0 + r;
            float2 v = make_float2(0.f, 0.f);
            if (grow < n)
                v = *(const float2*)(x + (size_t)grow * F + kc + kp * 2);
            xs[r * 20 + kp] = split_pack(v.x, v.y);
        }
        __syncthreads();

        #pragma unroll
        for (int ks = 0; ks < 2; ks++) {
            const int p0 = ks * 8 + tig;
            const int p1 = p0 + 4;

            // A fragments for both m-tiles
            uint32_t ah[2][4], al[2][4];
            #pragma unroll
            for (int mt = 0; mt < 2; mt++) {
                int r0 = wm * 32 + mt * 16 + gid;
                uint2 qa0 = xs[r0 * 20 + p0];
                uint2 qa1 = xs[(r0 + 8) * 20 + p0];
                uint2 qa2 = xs[r0 * 20 + p1];
                uint2 qa3 = xs[(r0 + 8) * 20 + p1];
                ah[mt][0] = qa0.x; ah[mt][1] = qa1.x; ah[mt][2] = qa2.x; ah[mt][3] = qa3.x;
                al[mt][0] = qa0.y; al[mt][1] = qa1.y; al[mt][2] = qa2.y; al[mt][3] = qa3.y;
            }

            #pragma unroll
            for (int nt = 0; nt < 4; nt++) {
                int nn = wn * 32 + nt * 8 + gid;
                uint2 qb0 = ws[nn * 20 + p0];
                uint2 qb1 = ws[nn * 20 + p1];
                uint32_t bh[2] = {qb0.x, qb1.x};
                uint32_t bl[2] = {qb0.y, qb1.y};
                #pragma unroll
                for (int mt = 0; mt < 2; mt++) {
                    mma_bf16(acc[mt][nt], ah[mt], bh);
                    mma_bf16(acc[mt][nt], al[mt], bh);
                    mma_bf16(acc[mt][nt], ah[mt], bl);
                }
            }
        }
    }

    // Epilogue
    #pragma unroll
    for (int mt = 0; mt < 2; mt++) {
        #pragma unroll
        for (int half = 0; half < 2; half++) {
            int grow = row0 + wm * 32 + mt * 16 + gid + half * 8;
            if (grow < n) {
                float* o = out + (size_t)grow * D_MP + wn * 32 + tig * 2;
                #pragma unroll
                for (int nt = 0; nt < 4; nt++) {
                    float2 v = half ? make_float2(acc[mt][nt][2], acc[mt][nt][3])
                                    : make_float2(acc[mt][nt][0], acc[mt][nt][1]);
                    *(float2*)(o + nt * 8) = v;
                }
            }
        }
    }
}

// ===========================================================================
// CSR build
// ===========================================================================
__global__ void hist_dual(const int* __restrict__ rowA, const int* __restrict__ rowP,
                          int* __restrict__ cntA, int* __restrict__ cntP) {
    int i = blockIdx.x * blockDim.x + threadIdx.x;
    if (i < E_NNZ) {
        atomicAdd(&cntA[rowA[i]], 1);
    } else if (i < 2 * E_NNZ) {
        atomicAdd(&cntP[rowP[i - E_NNZ]], 1);
    }
}

#define SCAN_CHUNK 2048

__global__ void scan_pass1_dual(const int* __restrict__ cntA, int* __restrict__ bsA, int nA,
                                const int* __restrict__ cntP, int* __restrict__ bsP, int nP,
                                int nbA) {
    __shared__ int sh[256];
    const int* cnt = (blockIdx.x < nbA) ? cntA : cntP;
    int*       bs  = (blockIdx.x < nbA) ? bsA  : bsP;
    int        n   = (blockIdx.x < nbA) ? nA   : nP;
    int        blk = (blockIdx.x < nbA) ? blockIdx.x : blockIdx.x - nbA;
    int base = blk * SCAN_CHUNK;
    int t = threadIdx.x;
    int s = 0;
    #pragma unroll
    for (int j = 0; j < 8; j++) {
        int i = base + t * 8 + j;
        if (i < n) s += cnt[i];
    }
    sh[t] = s;
    __syncthreads();
    for (int off = 128; off > 0; off >>= 1) {
        if (t < off) sh[t] += sh[t + off];
        __syncthreads();
    }
    if (t == 0) bs[blk] = sh[0];
}

__global__ void scan_pass2_dual(int* __restrict__ bsA, int nbA,
                                int* __restrict__ bsP, int nbP) {
    __shared__ int sh[128];
    int* bs = blockIdx.x ? bsP : bsA;
    int nb  = blockIdx.x ? nbP : nbA;
    int t = threadIdx.x;
    int v = (t < nb) ? bs[t] : 0;
    sh[t] = v;
    __syncthreads();
    for (int off = 1; off < 128; off <<= 1) {
        int xx = (t >= off) ? sh[t - off] : 0;
        __syncthreads();
        sh[t] += xx;
        __syncthreads();
    }
    if (t < nb) bs[t] = sh[t] - v;
}

__global__ void scan_pass3_dual(const int* __restrict__ cntA, const int* __restrict__ bsA,
                                int* __restrict__ ptrA, int nA,
                                const int* __restrict__ cntP, const int* __restrict__ bsP,
                                int* __restrict__ ptrP, int nP, int nbA) {
    __shared__ int sh[256];
    const int* cnt = (blockIdx.x < nbA) ? cntA : cntP;
    const int* bs  = (blockIdx.x < nbA) ? bsA  : bsP;
    int*       ptr = (blockIdx.x < nbA) ? ptrA : ptrP;
    int        n   = (blockIdx.x < nbA) ? nA   : nP;
    int        blk = (blockIdx.x < nbA) ? blockIdx.x : blockIdx.x - nbA;
    int base = blk * SCAN_CHUNK;
    int t = threadIdx.x;
    int v[8];
    int s = 0;
    #pragma unroll
    for (int j = 0; j < 8; j++) {
        int i = base + t * 8 + j;
        v[j] = (i < n) ? cnt[i] : 0;
        s += v[j];
    }
    sh[t] = s;
    __syncthreads();
    for (int off = 1; off < 256; off <<= 1) {
        int xx = (t >= off) ? sh[t - off] : 0;
        __syncthreads();
        sh[t] += xx;
        __syncthreads();
    }
    int ex = sh[t] - s + bs[blk];
    #pragma unroll
    for (int j = 0; j < 8; j++) {
        int i = base + t * 8 + j;
        if (i < n) {
            ptr[i] = ex;
            ex += v[j];
            if (i == n - 1) ptr[n] = ex;
        }
    }
}

__global__ void scatter_dual(const int* __restrict__ rowA, const int* __restrict__ colA,
                             const float* __restrict__ valA,
                             const int* __restrict__ ptrA, int* __restrict__ curA,
                             int* __restrict__ ccolA, float* __restrict__ cvalA,
                             const int* __restrict__ rowP, const int* __restrict__ colP,
                             const float* __restrict__ valP,
                             const int* __restrict__ ptrP, int* __restrict__ curP,
                             int* __restrict__ ccolP, float* __restrict__ cvalP) {
    int i = blockIdx.x * blockDim.x + threadIdx.x;
    if (i < E_NNZ) {
        int r = rowA[i];
        int p = ptrA[r] + atomicAdd(&curA[r], 1);
        ccolA[p] = colA[i];
        cvalA[p] = valA[i];
    } else if (i < 2 * E_NNZ) {
        int j = i - E_NNZ;
        int r = rowP[j];
        int p = ptrP[r] + atomicAdd(&curP[r], 1);
        ccolP[p] = colP[j];
        cvalP[p] = valP[j];
    }
}

// ===========================================================================
// CSR SpMM: warp per row, 2-way unrolled edge loop per 16-lane half
// ===========================================================================
__global__ void spmm_csr_kernel(const int* __restrict__ ptr,
                                const int* __restrict__ ccol,
                                const float* __restrict__ cval,
                                const float* __restrict__ z,
                                float* __restrict__ out, int nrows) {
    int w = (blockIdx.x * blockDim.x + threadIdx.x) >> 5;
    if (w >= nrows) return;
    int lane = threadIdx.x & 31;
    int half = lane >> 4;
    int s    = lane & 15;

    int beg = ptr[w], end = ptr[w + 1];
    float4 acc0 = make_float4(0.f, 0.f, 0.f, 0.f);
    float4 acc1 = make_float4(0.f, 0.f, 0.f, 0.f);

    int e = beg + half;
    for (; e + 2 < end; e += 4) {
        int   c0 = __ldg(ccol + e);
        float v0 = __ldg(cval + e);
        int   c1 = __ldg(ccol + e + 2);
        float v1 = __ldg(cval + e + 2);
        float4 z0 = __ldg((const float4*)(z + (size_t)c0 * D_MP) + s);
        float4 z1 = __ldg((const float4*)(z + (size_t)c1 * D_MP) + s);
        acc0.x = fmaf(v0, z0.x, acc0.x);
        acc0.y = fmaf(v0, z0.y, acc0.y);
        acc0.z = fmaf(v0, z0.z, acc0.z);
        acc0.w = fmaf(v0, z0.w, acc0.w);
        acc1.x = fmaf(v1, z1.x, acc1.x);
        acc1.y = fmaf(v1, z1.y, acc1.y);
        acc1.z = fmaf(v1, z1.z, acc1.z);
        acc1.w = fmaf(v1, z1.w, acc1.w);
    }
    if (e < end) {
        int   c = __ldg(ccol + e);
        float v = __ldg(cval + e);
        float4 zv = __ldg((const float4*)(z + (size_t)c * D_MP) + s);
        acc0.x = fmaf(v, zv.x, acc0.x);
        acc0.y = fmaf(v, zv.y, acc0.y);
        acc0.z = fmaf(v, zv.z, acc0.z);
        acc0.w = fmaf(v, zv.w, acc0.w);
    }
    acc0.x += acc1.x; acc0.y += acc1.y; acc0.z += acc1.z; acc0.w += acc1.w;

    acc0.x += __shfl_xor_sync(0xffffffffu, acc0.x, 16);
    acc0.y += __shfl_xor_sync(0xffffffffu, acc0.y, 16);
    acc0.z += __shfl_xor_sync(0xffffffffu, acc0.z, 16);
    acc0.w += __shfl_xor_sync(0xffffffffu, acc0.w, 16);
    if (half == 0)
        *((float4*)(out + (size_t)w * D_MP) + s) = acc0;
}

// ===========================================================================
// Launch
// ===========================================================================
extern "C" void kernel_launch(void* const* d_in, const int* in_sizes, int n_in,
                              void* d_out, int out_size) {
    const float* x_paper  = (const float*)d_in[0];
    const float* x_author = (const float*)d_in[1];
    const float* W_paper  = (const float*)d_in[2];
    const float* W_author = (const float*)d_in[3];
    const int*   pa_row   = (const int*)  d_in[4];
    const int*   pa_col   = (const int*)  d_in[5];
    const float* pa_val   = (const float*)d_in[6];
    const int*   ap_row   = (const int*)  d_in[7];
    const int*   ap_col   = (const int*)  d_in[8];
    const float* ap_val   = (const float*)d_in[9];

    float* out       = (float*)d_out;
    float* out_pap   = out;
    float* out_papap = out + (size_t)N_P * D_MP;
    float* out_apa   = out + (size_t)2 * N_P * D_MP;

    float *bufP, *bufA1, *bufA2;
    int *pa_ptr, *ap_ptr, *pa_ccol, *ap_ccol, *cnt, *bsumA, *bsumP;
    float *pa_cval, *ap_cval;
    cudaGetSymbolAddress((void**)&bufP,    g_bufP);
    cudaGetSymbolAddress((void**)&bufA1,   g_bufA1);
    cudaGetSymbolAddress((void**)&bufA2,   g_bufA2);
    cudaGetSymbolAddress((void**)&pa_ptr,  g_pa_ptr);
    cudaGetSymbolAddress((void**)&ap_ptr,  g_ap_ptr);
    cudaGetSymbolAddress((void**)&pa_ccol, g_pa_ccol);
    cudaGetSymbolAddress((void**)&pa_cval, g_pa_cval);
    cudaGetSymbolAddress((void**)&ap_ccol, g_ap_ccol);
    cudaGetSymbolAddress((void**)&ap_cval, g_ap_cval);
    cudaGetSymbolAddress((void**)&cnt,     g_cnt);
    cudaGetSymbolAddress((void**)&bsumA,   g_bsumA);
    cudaGetSymbolAddress((void**)&bsumP,   g_bsumP);

    int* cntA = cnt;
    int* curA = cnt + N_A;
    int* cntP = cnt + 2 * N_A;
    int* curP = cnt + 2 * N_A + N_P;

    cudaMemsetAsync(cnt, 0, (size_t)2 * (N_P + N_A) * sizeof(int));

    const int HB = 256;
    const int dgrid = (2 * E_NNZ + HB - 1) / HB;
    const int nbA = (N_A + SCAN_CHUNK - 1) / SCAN_CHUNK;
    const int nbP = (N_P + SCAN_CHUNK - 1) / SCAN_CHUNK;

    // kernel order: 4th kernel node (ncu capture slot) is gemmP
    hist_dual<<<dgrid, HB>>>(pa_row, ap_row, cntA, cntP);                         // 0
    scan_pass1_dual<<<nbA + nbP, 256>>>(cntA, bsumA, N_A, cntP, bsumP, N_P, nbA); // 1
    scan_pass2_dual<<<2, 128>>>(bsumA, nbA, bsumP, nbP);                          // 2
    gemm_bf16x3<F_P><<<(N_P + 127) / 128, 256>>>(x_paper,  W_paper,  bufP,  N_P); // 3 <- profiled
    gemm_bf16x3<F_A><<<(N_A + 127) / 128, 256>>>(x_author, W_author, bufA1, N_A); // 4
    scan_pass3_dual<<<nbA + nbP, 256>>>(cntA, bsumA, pa_ptr, N_A,
                                        cntP, bsumP, ap_ptr, N_P, nbA);           // 5
    scatter_dual<<<dgrid, HB>>>(pa_row, pa_col, pa_val, pa_ptr, curA, pa_ccol, pa_cval,
                                ap_row, ap_col, ap_val, ap_ptr, curP, ap_ccol, ap_cval); // 6

    auto sblocks = [](int nrows) { return (nrows * 32 + 255) / 256; };

    // P-A-P
    spmm_csr_kernel<<<sblocks(N_A), 256>>>(pa_ptr, pa_ccol, pa_cval, bufP,  bufA2,   N_A);
    spmm_csr_kernel<<<sblocks(N_P), 256>>>(ap_ptr, ap_ccol, ap_cval, bufA2, out_pap, N_P);
    // P-A-P-A-P
    spmm_csr_kernel<<<sblocks(N_A), 256>>>(pa_ptr, pa_ccol, pa_cval, out_pap, bufA2,     N_A);
    spmm_csr_kernel<<<sblocks(N_P), 256>>>(ap_ptr, ap_ccol, ap_cval, bufA2,   out_papap, N_P);
    // A-P-A
    spmm_csr_kernel<<<sblocks(N_P), 256>>>(ap_ptr, ap_ccol, ap_cval, bufA1, bufP,    N_P);
    spmm_csr_kernel<<<sblocks(N_A), 256>>>(pa_ptr, pa_ccol, pa_cval, bufP,  out_apa, N_A);
}